// round 2
// baseline (speedup 1.0000x reference)
#include <cuda_runtime.h>
#include <math.h>

#define T_LEN 512
#define BATCH 64
#define HID   512
#define GATES 2048
#define NBLK  64
#define HPAD  516     // row pitch (floats) for sB/sH: stride 516 -> conflict-free frag loads
#define PPITCH 36     // partials row pitch

// ---------------------------------------------------------------------------
// Static device scratch
// ---------------------------------------------------------------------------
__device__ float g_xg[(size_t)T_LEN * BATCH * GATES];   // 256 MB input projections
__device__ float g_hseq[(size_t)T_LEN * BATCH * HID];   //  64 MB layer-0 hidden sequence
__device__ float g_h2[2 * BATCH * HID];                 // layer-1 hidden double buffer
__device__ float g_zero[BATCH * HID];                   // permanent zeros (h_{-1})
__device__ volatile unsigned g_flags[NBLK];             // grid barrier flags

// ---------------------------------------------------------------------------
// TF32 helpers
// ---------------------------------------------------------------------------
__device__ __forceinline__ unsigned f2tf(float f) {
    unsigned u;
    asm("cvt.rna.tf32.f32 %0, %1;" : "=r"(u) : "f"(f));
    return u;
}
__device__ __forceinline__ float tfr(float f) { return __uint_as_float(f2tf(f)); }

__device__ __forceinline__ void mma_m16n8k8(float c[4], const unsigned a[4], const unsigned b[2]) {
    asm volatile(
        "mma.sync.aligned.m16n8k8.row.col.f32.tf32.tf32.f32 "
        "{%0,%1,%2,%3}, {%4,%5,%6,%7}, {%8,%9}, {%0,%1,%2,%3};"
        : "+f"(c[0]), "+f"(c[1]), "+f"(c[2]), "+f"(c[3])
        : "r"(a[0]), "r"(a[1]), "r"(a[2]), "r"(a[3]), "r"(b[0]), "r"(b[1]));
}

// Gate-interleaved column n = 4*j + gate  ->  original weight row r = gate*512 + j
__device__ __forceinline__ int remap_row(int n) { return ((n & 3) << 9) | (n >> 2); }

// ---------------------------------------------------------------------------
// Input-projection GEMM (unchanged from R0):
//   g_xg[row][n] = A[row,:] . W[remap(n),:] + bx[remap(n)] + bh[remap(n)]
//   mode 0: A row (t*64+b) = x[b][t][:] ; mode 1: A row = g_hseq[row][:]
// ---------------------------------------------------------------------------
__global__ void gemm_xproj(const float* __restrict__ A_x,
                           const float* __restrict__ W,
                           const float* __restrict__ bx,
                           const float* __restrict__ bh,
                           int mode) {
    __shared__ float As[128 * 36];
    __shared__ float Bs[64 * 36];

    const int m_blk = blockIdx.x * 128;
    const int n_blk = blockIdx.y * 64;
    const int tid = threadIdx.x;
    const int w = tid >> 5;
    const int lane = tid & 31;
    const int gi = lane >> 2;
    const int ti = lane & 3;
    const int mw = (w & 3) * 32;
    const int nw = (w >> 2) * 32;

    float acc[2][4][4];
#pragma unroll
    for (int a = 0; a < 2; a++)
#pragma unroll
        for (int b = 0; b < 4; b++)
#pragma unroll
            for (int c = 0; c < 4; c++) acc[a][b][c] = 0.f;

    for (int k0 = 0; k0 < 512; k0 += 32) {
#pragma unroll
        for (int v = tid; v < 128 * 8; v += 256) {
            int row = v >> 3, c4 = (v & 7) * 4;
            int grow = m_blk + row;
            const float* ap;
            if (mode == 0)
                ap = A_x + (size_t)((grow & 63) * 512 + (grow >> 6)) * 512;
            else
                ap = g_hseq + (size_t)grow * 512;
            float4 f = *(const float4*)(ap + k0 + c4);
            As[row * 36 + c4 + 0] = tfr(f.x);
            As[row * 36 + c4 + 1] = tfr(f.y);
            As[row * 36 + c4 + 2] = tfr(f.z);
            As[row * 36 + c4 + 3] = tfr(f.w);
        }
#pragma unroll
        for (int v = tid; v < 64 * 8; v += 256) {
            int row = v >> 3, c4 = (v & 7) * 4;
            int r = remap_row(n_blk + row);
            float4 f = *(const float4*)(W + (size_t)r * 512 + k0 + c4);
            Bs[row * 36 + c4 + 0] = tfr(f.x);
            Bs[row * 36 + c4 + 1] = tfr(f.y);
            Bs[row * 36 + c4 + 2] = tfr(f.z);
            Bs[row * 36 + c4 + 3] = tfr(f.w);
        }
        __syncthreads();

#pragma unroll
        for (int kk = 0; kk < 4; kk++) {
            unsigned afr[2][4];
#pragma unroll
            for (int mt = 0; mt < 2; mt++) {
                int r = mw + mt * 16;
                afr[mt][0] = __float_as_uint(As[(r + gi) * 36 + kk * 8 + ti]);
                afr[mt][1] = __float_as_uint(As[(r + gi + 8) * 36 + kk * 8 + ti]);
                afr[mt][2] = __float_as_uint(As[(r + gi) * 36 + kk * 8 + ti + 4]);
                afr[mt][3] = __float_as_uint(As[(r + gi + 8) * 36 + kk * 8 + ti + 4]);
            }
#pragma unroll
            for (int nt = 0; nt < 4; nt++) {
                unsigned bfr[2];
                bfr[0] = __float_as_uint(Bs[(nw + nt * 8 + gi) * 36 + kk * 8 + ti]);
                bfr[1] = __float_as_uint(Bs[(nw + nt * 8 + gi) * 36 + kk * 8 + ti + 4]);
#pragma unroll
                for (int mt = 0; mt < 2; mt++) mma_m16n8k8(acc[mt][nt], afr[mt], bfr);
            }
        }
        __syncthreads();
    }

#pragma unroll
    for (int mt = 0; mt < 2; mt++) {
        int row = m_blk + mw + mt * 16 + gi;
#pragma unroll
        for (int nt = 0; nt < 4; nt++) {
            int col = n_blk + nw + nt * 8 + 2 * ti;
            int r0 = remap_row(col);
            int r1 = remap_row(col + 1);
            float b0v = bx[r0] + bh[r0];
            float b1v = bx[r1] + bh[r1];
            float2 v0 = make_float2(acc[mt][nt][0] + b0v, acc[mt][nt][1] + b1v);
            float2 v1 = make_float2(acc[mt][nt][2] + b0v, acc[mt][nt][3] + b1v);
            *(float2*)(g_xg + (size_t)row * 2048 + col) = v0;
            *(float2*)(g_xg + (size_t)(row + 8) * 2048 + col) = v1;
        }
    }
}

// ---------------------------------------------------------------------------
// Persistent per-layer LSTM kernel.
// 64 blocks (co-resident, 1/SM), 256 threads (8 warps).
// Block b owns 32 interleaved gate cols [n_blk, n_blk+32) and all 64 batch rows.
// Warp w reduces K-slice [64w, 64w+64); partials summed via SMEM.
// SMEM: sB weights [32][HPAD] (staged once) | sH h-stage [64][HPAD] (per step,
//       aliased by partials after compute) | sC cell state [64][8] (persistent).
// ---------------------------------------------------------------------------
extern "C" __global__ void __launch_bounds__(256, 1)
lstm_persist(const float* __restrict__ Wh, int layer, float* __restrict__ final_out) {
    extern __shared__ float smem[];
    float* sB = smem;                                // 32*HPAD = 66048 B
    float* sH = smem + 32 * HPAD;                    // 64*HPAD = 132096 B
    float* sC = smem + 32 * HPAD + 64 * HPAD;        // 2048 B
    float* sP = sH;                                  // partials alias: [8][64][PPITCH]

    const int tid = threadIdx.x;
    const int w = tid >> 5;
    const int lane = tid & 31;
    const int gi = lane >> 2;
    const int ti = lane & 3;
    const int n_blk = blockIdx.x * 32;
    const int kbase = w * 64;

    // Stage weights once (remapped rows, tf32-rounded)
    for (int v = tid; v < 32 * 128; v += 256) {
        int row = v >> 7, c4 = (v & 127) * 4;
        int r = remap_row(n_blk + row);
        float4 f = *(const float4*)(Wh + (size_t)r * 512 + c4);
        float* d = sB + row * HPAD + c4;
        d[0] = tfr(f.x); d[1] = tfr(f.y); d[2] = tfr(f.z); d[3] = tfr(f.w);
    }
    // Init cell state
    for (int v = tid; v < 64 * 8; v += 256) sC[v] = 0.f;
    __syncthreads();

    for (int t = 0; t < T_LEN; t++) {
        const float* h_prev;
        float* h_out;
        if (layer == 0) {
            h_prev = (t == 0) ? g_zero : (g_hseq + (size_t)(t - 1) * BATCH * HID);
            h_out = g_hseq + (size_t)t * BATCH * HID;
        } else {
            h_prev = (t == 0) ? g_zero : (g_h2 + (size_t)(t & 1) * BATCH * HID);
            h_out = (t == T_LEN - 1) ? final_out
                                     : (g_h2 + (size_t)((t + 1) & 1) * BATCH * HID);
        }

        // Stage h_prev [64][512] -> sH (L2-only loads: layer-1 buffers alias across steps)
        for (int v = tid; v < 64 * 128; v += 256) {
            int row = v >> 7, c4 = (v & 127) * 4;
            float4 f = __ldcg((const float4*)(h_prev + (size_t)row * 512 + c4));
            float* d = sH + row * HPAD + c4;
            d[0] = tfr(f.x); d[1] = tfr(f.y); d[2] = tfr(f.z); d[3] = tfr(f.w);
        }
        __syncthreads();

        // Compute: warp w does partial gates[64][32] over its K-slice
        float acc[4][4][4];
#pragma unroll
        for (int a = 0; a < 4; a++)
#pragma unroll
            for (int b = 0; b < 4; b++)
#pragma unroll
                for (int c = 0; c < 4; c++) acc[a][b][c] = 0.f;

#pragma unroll
        for (int kc = 0; kc < 8; kc++) {
            int k0 = kbase + kc * 8;
            unsigned afr[4][4];
#pragma unroll
            for (int mt = 0; mt < 4; mt++) {
                int r = mt * 16;
                afr[mt][0] = __float_as_uint(sH[(r + gi) * HPAD + k0 + ti]);
                afr[mt][1] = __float_as_uint(sH[(r + gi + 8) * HPAD + k0 + ti]);
                afr[mt][2] = __float_as_uint(sH[(r + gi) * HPAD + k0 + ti + 4]);
                afr[mt][3] = __float_as_uint(sH[(r + gi + 8) * HPAD + k0 + ti + 4]);
            }
#pragma unroll
            for (int nt = 0; nt < 4; nt++) {
                unsigned bfr[2];
                bfr[0] = __float_as_uint(sB[(nt * 8 + gi) * HPAD + k0 + ti]);
                bfr[1] = __float_as_uint(sB[(nt * 8 + gi) * HPAD + k0 + ti + 4]);
#pragma unroll
                for (int mt = 0; mt < 4; mt++) mma_m16n8k8(acc[mt][nt], afr[mt], bfr);
            }
        }
        __syncthreads();   // all warps done reading sH before partials overwrite it

        // Write partials: sP[w][m][n] (PPITCH pitch)
#pragma unroll
        for (int mt = 0; mt < 4; mt++) {
#pragma unroll
            for (int nt = 0; nt < 4; nt++) {
                int m = mt * 16 + gi;
                int n = nt * 8 + 2 * ti;
                float* base = sP + ((size_t)w * 64 + m) * PPITCH + n;
                *(float2*)base = make_float2(acc[mt][nt][0], acc[mt][nt][1]);
                *(float2*)(base + 8 * PPITCH) = make_float2(acc[mt][nt][2], acc[mt][nt][3]);
            }
        }
        __syncthreads();

        // Reduce 8 partials + gate math + state update. 512 quads, 2 per thread.
        const float* xg_t = g_xg + (size_t)t * BATCH * GATES;
#pragma unroll
        for (int qq = 0; qq < 2; qq++) {
            int q = tid + qq * 256;
            int b = q >> 3, j = q & 7;
            float4 s = make_float4(0.f, 0.f, 0.f, 0.f);
#pragma unroll
            for (int pw = 0; pw < 8; pw++) {
                float4 p = *(const float4*)(sP + ((size_t)pw * 64 + b) * PPITCH + j * 4);
                s.x += p.x; s.y += p.y; s.z += p.z; s.w += p.w;
            }
            float4 xg4 = __ldcg((const float4*)(xg_t + (size_t)b * 2048 + n_blk + j * 4));
            float fg = s.x + xg4.x;
            float ig = s.y + xg4.y;
            float gg = s.z + xg4.z;
            float og = s.w + xg4.w;
            fg = 1.f / (1.f + expf(-fg));
            ig = 1.f / (1.f + expf(-ig));
            gg = tanhf(gg);
            og = 1.f / (1.f + expf(-og));
            float c = sC[b * 8 + j];
            c = fg * c + ig * gg;
            sC[b * 8 + j] = c;
            h_out[(size_t)b * 512 + (n_blk >> 2) + j] = og * tanhf(c);
        }

        // Grid barrier (monotonic targets across both layers; reset per launch)
        __threadfence();
        __syncthreads();
        unsigned target = (unsigned)(layer * T_LEN + t + 1);
        if (tid == 0) g_flags[blockIdx.x] = target;
        if (tid < NBLK) {
            while (g_flags[tid] < target) { }
            __threadfence();
        }
        __syncthreads();
    }
}

// ---------------------------------------------------------------------------
// Per-launch reset (makes graph replays deterministic)
// ---------------------------------------------------------------------------
__global__ void reset_flags() {
    if (threadIdx.x < NBLK) g_flags[threadIdx.x] = 0;
}

// ---------------------------------------------------------------------------
// Launch sequence: 5 graph nodes
// ---------------------------------------------------------------------------
extern "C" void kernel_launch(void* const* d_in, const int* in_sizes, int n_in,
                              void* d_out, int out_size) {
    const float* x   = (const float*)d_in[0];
    const float* Wx0 = (const float*)d_in[1];
    const float* bx0 = (const float*)d_in[2];
    const float* Wh0 = (const float*)d_in[3];
    const float* bh0 = (const float*)d_in[4];
    const float* Wx1 = (const float*)d_in[5];
    const float* bx1 = (const float*)d_in[6];
    const float* Wh1 = (const float*)d_in[7];
    const float* bh1 = (const float*)d_in[8];

    static const size_t SMEM_BYTES = (32 * HPAD + 64 * HPAD + 64 * 8) * sizeof(float);
    cudaFuncSetAttribute(lstm_persist, cudaFuncAttributeMaxDynamicSharedMemorySize,
                         (int)SMEM_BYTES);

    dim3 gemm_grid(256, 32);

    reset_flags<<<1, 64>>>();
    gemm_xproj<<<gemm_grid, 256>>>(x, Wx0, bx0, bh0, 0);
    lstm_persist<<<NBLK, 256, SMEM_BYTES>>>(Wh0, 0, nullptr);
    gemm_xproj<<<gemm_grid, 256>>>(x /*unused*/, Wx1, bx1, bh1, 1);
    lstm_persist<<<NBLK, 256, SMEM_BYTES>>>(Wh1, 1, (float*)d_out);
}

// round 3
// speedup vs baseline: 2.1517x; 2.1517x over previous
#include <cuda_runtime.h>
#include <math.h>

#define T_LEN 512
#define BATCH 64
#define HID   512
#define WPITCH 1036   // weight row pitch (mod 32 = 12 -> conflict-free frag loads)
#define APITCH 268    // stage row pitch (mod 32 = 12 -> conflict-free frag loads)
#define PPITCH 33     // partials pitch (odd -> conflict-free scalar reduce)

// ---------------------------------------------------------------------------
// Static device scratch
// ---------------------------------------------------------------------------
__device__ float g_hseq[(size_t)T_LEN * BATCH * HID];   // 64 MB: layer-0 hidden sequence
__device__ float g_h2[2 * BATCH * HID];                 // layer-1 hidden double buffer
__device__ volatile unsigned g_flags0[64];              // layer-0 step flags
__device__ volatile unsigned g_flags1[64];              // layer-1 step flags

// ---------------------------------------------------------------------------
// TF32 helpers
// ---------------------------------------------------------------------------
__device__ __forceinline__ unsigned f2tf(float f) {
    unsigned u;
    asm("cvt.rna.tf32.f32 %0, %1;" : "=r"(u) : "f"(f));
    return u;
}
__device__ __forceinline__ float tfr(float f) { return __uint_as_float(f2tf(f)); }

__device__ __forceinline__ void mma_m16n8k8(float c[4], const unsigned a[4], const unsigned b[2]) {
    asm volatile(
        "mma.sync.aligned.m16n8k8.row.col.f32.tf32.tf32.f32 "
        "{%0,%1,%2,%3}, {%4,%5,%6,%7}, {%8,%9}, {%0,%1,%2,%3};"
        : "+f"(c[0]), "+f"(c[1]), "+f"(c[2]), "+f"(c[3])
        : "r"(a[0]), "r"(a[1]), "r"(a[2]), "r"(a[3]), "r"(b[0]), "r"(b[1]));
}

// Gate-interleaved column n = 4*j + gate  ->  original weight row r = gate*512 + j
__device__ __forceinline__ int remap_row(int n) { return ((n & 3) << 9) | (n >> 2); }

// ---------------------------------------------------------------------------
// Stage-load helpers: 64 rows x 256 cols (one K-phase) cooperatively.
// ---------------------------------------------------------------------------
__device__ __forceinline__ void ldg16(float4* r, const float* __restrict__ src,
                                      size_t stride, int koff, int tid) {
#pragma unroll
    for (int i = 0; i < 16; i++) {
        int v = tid + (i << 8);
        int row = v >> 6, c = (v & 63) << 2;
        r[i] = __ldcg((const float4*)(src + (size_t)row * stride + koff + c));
    }
}
__device__ __forceinline__ void sts16(const float4* r, float* sA, int tid) {
#pragma unroll
    for (int i = 0; i < 16; i++) {
        int v = tid + (i << 8);
        int row = v >> 6, c = (v & 63) << 2;
        float4 o;
        o.x = tfr(r[i].x); o.y = tfr(r[i].y); o.z = tfr(r[i].z); o.w = tfr(r[i].w);
        *(float4*)(sA + row * APITCH + c) = o;
    }
}

// One 256-wide K-phase of MMAs. Warp w covers stage-k [32w, 32w+32).
__device__ __forceinline__ void mma_phase(float acc[4][4][4], const float* sA,
                                          const float* sW, int wkbase,
                                          int kw, int gi, int ti) {
#pragma unroll
    for (int kc = 0; kc < 4; kc++) {
        int kl = kw + (kc << 3);
        unsigned afr[4][4];
#pragma unroll
        for (int mt = 0; mt < 4; mt++) {
            int r = mt * 16;
            afr[mt][0] = __float_as_uint(sA[(r + gi) * APITCH + kl + ti]);
            afr[mt][1] = __float_as_uint(sA[(r + gi + 8) * APITCH + kl + ti]);
            afr[mt][2] = __float_as_uint(sA[(r + gi) * APITCH + kl + ti + 4]);
            afr[mt][3] = __float_as_uint(sA[(r + gi + 8) * APITCH + kl + ti + 4]);
        }
#pragma unroll
        for (int nt = 0; nt < 4; nt++) {
            unsigned bfr[2];
            bfr[0] = __float_as_uint(sW[(nt * 8 + gi) * WPITCH + wkbase + kl + ti]);
            bfr[1] = __float_as_uint(sW[(nt * 8 + gi) * WPITCH + wkbase + kl + ti + 4]);
#pragma unroll
            for (int mt = 0; mt < 4; mt++) mma_m16n8k8(acc[mt][nt], afr[mt], bfr);
        }
    }
}

// ---------------------------------------------------------------------------
// Fused dual-layer persistent LSTM.
// 128 blocks: 0..63 layer 0, 64..127 layer 1. 256 threads (8 warps) each.
// Block owns 32 interleaved gate cols; weights [Wx;Wh] slice (32x1024 tf32)
// resident in SMEM. Per step: gates = [opA; opB] @ Wcat^T via 4 K-phases of
// 256 through one stage buffer, register prefetch of next half under MMA.
// ---------------------------------------------------------------------------
extern "C" __global__ void __launch_bounds__(256, 1)
lstm_fused(const float* __restrict__ x,
           const float* __restrict__ Wx0, const float* __restrict__ bx0,
           const float* __restrict__ Wh0, const float* __restrict__ bh0,
           const float* __restrict__ Wx1, const float* __restrict__ bx1,
           const float* __restrict__ Wh1, const float* __restrict__ bh1,
           float* __restrict__ out) {
    extern __shared__ float smem[];
    float* sW = smem;                         // 32*WPITCH floats
    float* sA = smem + 32 * WPITCH;           // 64*APITCH floats (stage; aliased by partials)
    float* sC = sA + 64 * APITCH;             // 512 floats cell state
    float* sBias = sC + 512;                  // 32 floats
    float* sP = sA;                           // partials alias: 8*64*PPITCH <= 64*APITCH

    const int tid = threadIdx.x;
    const int w = tid >> 5;
    const int lane = tid & 31;
    const int gi = lane >> 2;
    const int ti = lane & 3;
    const int layer = blockIdx.x >> 6;
    const int bslot = blockIdx.x & 63;
    const int n_blk = bslot * 32;
    const int kw = w << 5;   // warp K offset within a 256-wide phase

    const float* Wx = layer ? Wx1 : Wx0;
    const float* Wh = layer ? Wh1 : Wh0;
    const float* bx = layer ? bx1 : bx0;
    const float* bh = layer ? bh1 : bh0;

    // Stage concatenated weights [Wx | Wh] (remapped rows, tf32-rounded), once.
    for (int v = tid; v < 32 * 128; v += 256) {
        int row = v >> 7, c4 = (v & 127) * 4;
        int r = remap_row(n_blk + row);
        float4 fx = *(const float4*)(Wx + (size_t)r * 512 + c4);
        float4 fh = *(const float4*)(Wh + (size_t)r * 512 + c4);
        float* dx = sW + (size_t)row * WPITCH + c4;
        dx[0] = tfr(fx.x); dx[1] = tfr(fx.y); dx[2] = tfr(fx.z); dx[3] = tfr(fx.w);
        float* dh = dx + 512;
        dh[0] = tfr(fh.x); dh[1] = tfr(fh.y); dh[2] = tfr(fh.z); dh[3] = tfr(fh.w);
    }
    if (tid < 32) {
        int r = remap_row(n_blk + tid);
        sBias[tid] = bx[r] + bh[r];
    }
    for (int v = tid; v < 512; v += 256) sC[v] = 0.f;
    __syncthreads();

    float4 pre[16];

    for (int t = 0; t < T_LEN; t++) {
        float acc[4][4][4];
#pragma unroll
        for (int a = 0; a < 4; a++)
#pragma unroll
            for (int b = 0; b < 4; b++)
#pragma unroll
                for (int c = 0; c < 4; c++) acc[a][b][c] = 0.f;

#pragma unroll 1
        for (int op = 0; op < 2; op++) {
            const float* src;
            size_t stride;
            int wbase;
            bool skip = false;
            if (layer == 0) {
                if (op == 0) {                       // x_t  (no wait)
                    src = x + (size_t)t * HID;       // x[b][t][:] : row stride T*D
                    stride = (size_t)T_LEN * HID;
                    wbase = 0;
                } else {                             // h1_{t-1}: wait peers step t
                    skip = (t == 0);
                    src = g_hseq + (size_t)(t - 1) * BATCH * HID;
                    stride = HID;
                    wbase = 512;
                    if (!skip) {
                        if (tid < 64) {
                            while (g_flags0[tid] < (unsigned)t) { }
                            __threadfence();
                        }
                        __syncthreads();
                    }
                }
            } else {
                if (op == 0) {                       // h2_{t-1}: own cohort, step t
                    skip = (t == 0);
                    src = g_h2 + (size_t)((t + 1) & 1) * BATCH * HID;
                    stride = HID;
                    wbase = 512;
                    if (!skip) {
                        if (tid < 64) {
                            while (g_flags1[tid] < (unsigned)t) { }
                            __threadfence();
                        }
                        __syncthreads();
                    }
                } else {                             // h1_t from layer 0
                    src = g_hseq + (size_t)t * BATCH * HID;
                    stride = HID;
                    wbase = 0;
                    if (tid < 64) {
                        while (g_flags0[tid] < (unsigned)(t + 1)) { }
                        __threadfence();
                    }
                    __syncthreads();
                }
            }
            if (skip) continue;

            // half 0: load + store stage
            ldg16(pre, src, stride, 0, tid);
            sts16(pre, sA, tid);
            __syncthreads();
            // prefetch half 1 under half-0 MMA
            ldg16(pre, src, stride, 256, tid);
            mma_phase(acc, sA, sW, wbase, kw, gi, ti);
            __syncthreads();
            sts16(pre, sA, tid);
            __syncthreads();
            mma_phase(acc, sA, sW, wbase + 256, kw, gi, ti);
            __syncthreads();
        }

        // Write K-split partials (pitch 33, scalar: bank = (m+n) -> ~2-way worst)
#pragma unroll
        for (int mt = 0; mt < 4; mt++) {
#pragma unroll
            for (int nt = 0; nt < 4; nt++) {
                int m = mt * 16 + gi;
                int n = nt * 8 + 2 * ti;
                int base = (w * 64 + m) * PPITCH + n;
                sP[base]     = acc[mt][nt][0];
                sP[base + 1] = acc[mt][nt][1];
                sP[base + 8 * PPITCH]     = acc[mt][nt][2];
                sP[base + 8 * PPITCH + 1] = acc[mt][nt][3];
            }
        }
        __syncthreads();

        // Reduce 8 partials + biases + gate math + state update.
        float* h_out;
        if (layer == 0)
            h_out = g_hseq + (size_t)t * BATCH * HID;
        else
            h_out = (t == T_LEN - 1) ? out : (g_h2 + (size_t)(t & 1) * BATCH * HID);

#pragma unroll
        for (int qq = 0; qq < 2; qq++) {
            int q = tid + (qq << 8);
            int b = q >> 3, j = q & 7;
            float s0 = 0.f, s1 = 0.f, s2 = 0.f, s3 = 0.f;
#pragma unroll
            for (int pw = 0; pw < 8; pw++) {
                int rb = (pw * 64 + b) * PPITCH + j * 4;   // bank = (b + 4j + c): conflict-free
                s0 += sP[rb];
                s1 += sP[rb + 1];
                s2 += sP[rb + 2];
                s3 += sP[rb + 3];
            }
            float fg = s0 + sBias[j * 4 + 0];
            float ig = s1 + sBias[j * 4 + 1];
            float gg = s2 + sBias[j * 4 + 2];
            float og = s3 + sBias[j * 4 + 3];
            fg = 1.f / (1.f + __expf(-fg));
            ig = 1.f / (1.f + __expf(-ig));
            gg = tanhf(gg);
            og = 1.f / (1.f + __expf(-og));
            float c = sC[b * 8 + j];
            c = fg * c + ig * gg;
            sC[b * 8 + j] = c;
            h_out[(size_t)b * HID + (n_blk >> 2) + j] = og * tanhf(c);
        }

        // Publish: data -> fence -> flag
        __threadfence();
        __syncthreads();
        if (tid == 0) {
            if (layer == 0) g_flags0[bslot] = (unsigned)(t + 1);
            else            g_flags1[bslot] = (unsigned)(t + 1);
        }
    }
}

// ---------------------------------------------------------------------------
// Per-launch flag reset (replay determinism)
// ---------------------------------------------------------------------------
__global__ void reset_flags() {
    if (threadIdx.x < 64) {
        g_flags0[threadIdx.x] = 0;
        g_flags1[threadIdx.x] = 0;
    }
}

// ---------------------------------------------------------------------------
// Launch: 2 graph nodes
// ---------------------------------------------------------------------------
extern "C" void kernel_launch(void* const* d_in, const int* in_sizes, int n_in,
                              void* d_out, int out_size) {
    const float* x   = (const float*)d_in[0];
    const float* Wx0 = (const float*)d_in[1];
    const float* bx0 = (const float*)d_in[2];
    const float* Wh0 = (const float*)d_in[3];
    const float* bh0 = (const float*)d_in[4];
    const float* Wx1 = (const float*)d_in[5];
    const float* bx1 = (const float*)d_in[6];
    const float* Wh1 = (const float*)d_in[7];
    const float* bh1 = (const float*)d_in[8];

    const size_t SMEM_BYTES = (size_t)(32 * WPITCH + 64 * APITCH + 512 + 32) * sizeof(float);
    cudaFuncSetAttribute(lstm_fused, cudaFuncAttributeMaxDynamicSharedMemorySize,
                         (int)SMEM_BYTES);

    reset_flags<<<1, 64>>>();
    lstm_fused<<<128, 256, SMEM_BYTES>>>(x, Wx0, bx0, Wh0, bh0,
                                         Wx1, bx1, Wh1, bh1, (float*)d_out);
}

// round 4
// speedup vs baseline: 2.4788x; 1.1520x over previous
#include <cuda_runtime.h>
#include <math.h>

#define T_LEN 512
#define BATCH 64
#define HID   512
#define BH    (BATCH * HID)
#define WPITCH 1036   // weight row pitch: 1036 % 32 = 12 -> conflict-free frag LDS
#define SPITCH 132    // stage row pitch: 132 % 32 = 4 -> conflict-free frag LDS
#define SSIZE  (64 * SPITCH)   // 8448 floats per stage buffer
#define PPITCH 33     // partials pitch

// ---------------------------------------------------------------------------
// Static device scratch
// ---------------------------------------------------------------------------
__device__ float g_xr[(size_t)BATCH * T_LEN * HID];     // 64 MB tf32-rounded x
__device__ float g_hseq[(size_t)T_LEN * BH];            // 64 MB layer-0 hidden seq (tf32)
__device__ float g_h2[2 * BH];                          // layer-1 hidden double buffer (tf32)
__device__ unsigned g_cnt0[T_LEN];                      // layer-0 step counters
__device__ unsigned g_cnt1[T_LEN];                      // layer-1 step counters

// ---------------------------------------------------------------------------
// TF32 + MMA helpers
// ---------------------------------------------------------------------------
__device__ __forceinline__ unsigned f2tf(float f) {
    unsigned u;
    asm("cvt.rna.tf32.f32 %0, %1;" : "=r"(u) : "f"(f));
    return u;
}
__device__ __forceinline__ float tfr(float f) { return __uint_as_float(f2tf(f)); }

__device__ __forceinline__ void mma_m16n8k8(float c[4], const unsigned a[4], const unsigned b[2]) {
    asm volatile(
        "mma.sync.aligned.m16n8k8.row.col.f32.tf32.tf32.f32 "
        "{%0,%1,%2,%3}, {%4,%5,%6,%7}, {%8,%9}, {%0,%1,%2,%3};"
        : "+f"(c[0]), "+f"(c[1]), "+f"(c[2]), "+f"(c[3])
        : "r"(a[0]), "r"(a[1]), "r"(a[2]), "r"(a[3]), "r"(b[0]), "r"(b[1]));
}

// Gate-interleaved column n = 4*j + gate  ->  original weight row r = gate*512 + j
__device__ __forceinline__ int remap_row(int n) { return ((n & 3) << 9) | (n >> 2); }

__device__ __forceinline__ void cp_commit() {
    asm volatile("cp.async.commit_group;" ::: "memory");
}
__device__ __forceinline__ void cp_wait0() {
    asm volatile("cp.async.wait_group 0;" ::: "memory");
}

// Issue one 64x128 phase: 2048 16B chunks, 8 per thread (256 threads).
__device__ __forceinline__ void issue_phase(float* buf, const float* __restrict__ src,
                                            size_t stride, int koff, int tid) {
#pragma unroll
    for (int i = 0; i < 8; i++) {
        int v = tid + (i << 8);
        int row = v >> 5, chunk = v & 31;
        const float* g = src + (size_t)row * stride + koff + (chunk << 2);
        unsigned s = (unsigned)__cvta_generic_to_shared(buf + row * SPITCH + (chunk << 2));
        asm volatile("cp.async.cg.shared.global [%0], [%1], 16;" :: "r"(s), "l"(g));
    }
}

// One 128-wide K-phase of MMAs. Warp w covers stage-k [16w, 16w+16).
__device__ __forceinline__ void mma_phase(float acc[4][4][4], const float* sA,
                                          const float* sW, int wb,
                                          int w, int gi, int ti) {
#pragma unroll
    for (int kc = 0; kc < 2; kc++) {
        int kl = (w << 4) + (kc << 3);
        unsigned afr[4][4];
#pragma unroll
        for (int mt = 0; mt < 4; mt++) {
            int r = mt * 16;
            afr[mt][0] = __float_as_uint(sA[(r + gi) * SPITCH + kl + ti]);
            afr[mt][1] = __float_as_uint(sA[(r + gi + 8) * SPITCH + kl + ti]);
            afr[mt][2] = __float_as_uint(sA[(r + gi) * SPITCH + kl + ti + 4]);
            afr[mt][3] = __float_as_uint(sA[(r + gi + 8) * SPITCH + kl + ti + 4]);
        }
#pragma unroll
        for (int nt = 0; nt < 4; nt++) {
            unsigned bfr[2];
            bfr[0] = __float_as_uint(sW[(nt * 8 + gi) * WPITCH + wb + kl + ti]);
            bfr[1] = __float_as_uint(sW[(nt * 8 + gi) * WPITCH + wb + kl + ti + 4]);
#pragma unroll
            for (int mt = 0; mt < 4; mt++) mma_m16n8k8(acc[mt][nt], afr[mt], bfr);
        }
    }
}

__device__ __forceinline__ float fsig(float x) {
    return __fdividef(1.f, 1.f + __expf(-x));
}
__device__ __forceinline__ float ftanh(float x) {
    return 1.f - __fdividef(2.f, __expf(2.f * x) + 1.f);
}

// ---------------------------------------------------------------------------
// Fused dual-layer persistent LSTM with cp.async double-buffered pipeline.
// 128 blocks (64/layer), 256 threads (8 warps). Block owns 32 interleaved
// gate cols; concatenated weights [Wx|Wh] (32x1024 tf32) resident in SMEM.
// Per step: 8 phases of 128-K; cp.async for phase p+1 overlaps MMA of p.
// ---------------------------------------------------------------------------
extern "C" __global__ void __launch_bounds__(256, 1)
lstm_fused(const float* __restrict__ Wx0, const float* __restrict__ bx0,
           const float* __restrict__ Wh0, const float* __restrict__ bh0,
           const float* __restrict__ Wx1, const float* __restrict__ bx1,
           const float* __restrict__ Wh1, const float* __restrict__ bh1,
           float* __restrict__ out) {
    extern __shared__ float smem[];
    float* sW = smem;                          // 32*WPITCH
    float* sStage0 = smem + 32 * WPITCH;       // SSIZE
    float* sStage1 = sStage0 + SSIZE;          // SSIZE
    float* sC = sStage1 + SSIZE;               // 512
    float* sBias = sC + 512;                   // 32
    float* sP = sStage0;                       // partials alias both stage bufs (16896 floats)

    const int tid = threadIdx.x;
    const int w = tid >> 5;
    const int lane = tid & 31;
    const int gi = lane >> 2;
    const int ti = lane & 3;
    const int layer = blockIdx.x >> 6;
    const int bslot = blockIdx.x & 63;
    const int n_blk = bslot * 32;

    const float* Wx = layer ? Wx1 : Wx0;
    const float* Wh = layer ? Wh1 : Wh0;
    const float* bxp = layer ? bx1 : bx0;
    const float* bhp = layer ? bh1 : bh0;

    // Stage concatenated weights [Wx | Wh] once (remapped rows, tf32-rounded)
    for (int v = tid; v < 32 * 128; v += 256) {
        int row = v >> 7, c4 = (v & 127) * 4;
        int r = remap_row(n_blk + row);
        float4 fx = *(const float4*)(Wx + (size_t)r * 512 + c4);
        float4 fh = *(const float4*)(Wh + (size_t)r * 512 + c4);
        float* dx = sW + (size_t)row * WPITCH + c4;
        dx[0] = tfr(fx.x); dx[1] = tfr(fx.y); dx[2] = tfr(fx.z); dx[3] = tfr(fx.w);
        float* dh = dx + 512;
        dh[0] = tfr(fh.x); dh[1] = tfr(fh.y); dh[2] = tfr(fh.z); dh[3] = tfr(fh.w);
    }
    if (tid < 32) {
        int r = remap_row(n_blk + tid);
        sBias[tid] = bxp[r] + bhp[r];
    }
    for (int v = tid; v < 512; v += 256) sC[v] = 0.f;
    __syncthreads();

    float* bufs[2] = {sStage0, sStage1};

    for (int t = 0; t < T_LEN; t++) {
        float acc[4][4][4];
#pragma unroll
        for (int a = 0; a < 4; a++)
#pragma unroll
            for (int b = 0; b < 4; b++)
#pragma unroll
                for (int c = 0; c < 4; c++) acc[a][b][c] = 0.f;

        // Per-op source/weight-base/validity
        const float* src0; const float* src1;
        size_t strd0, strd1;
        int wb0, wb1;
        bool val0, val1;
        if (layer == 0) {
            src0 = g_xr + (size_t)t * 512;           // x[b][t][:]
            strd0 = (size_t)T_LEN * HID; wb0 = 0;   val0 = true;
            src1 = g_hseq + (size_t)(t - 1) * BH;
            strd1 = HID;                 wb1 = 512; val1 = (t > 0);
        } else {
            src0 = g_h2 + (size_t)((t + 1) & 1) * BH;
            strd0 = HID;                 wb0 = 512; val0 = (t > 0);
            src1 = g_hseq + (size_t)t * BH;
            strd1 = HID;                 wb1 = 0;   val1 = true;
        }

        // op0 dependency: L1 waits for own cohort's previous step
        if (layer == 1 && t > 0) {
            if (tid == 0) {
                while (((volatile unsigned*)g_cnt1)[t - 1] < 64u) { }
                __threadfence();
            }
            __syncthreads();
        }

        if (val0) issue_phase(bufs[0], src0, strd0, 0, tid);
        cp_commit();

#pragma unroll
        for (int p = 0; p < 8; p++) {
            cp_wait0();
            __syncthreads();
            if (p < 7) {
                const int pn = p + 1;
                if (pn == 4) {   // dependency for op1 (h1 for both layers)
                    if (layer == 0) {
                        if (t > 0) {
                            if (tid == 0) {
                                while (((volatile unsigned*)g_cnt0)[t - 1] < 64u) { }
                                __threadfence();
                            }
                            __syncthreads();
                        }
                    } else {
                        if (tid == 0) {
                            while (((volatile unsigned*)g_cnt0)[t] < 64u) { }
                            __threadfence();
                        }
                        __syncthreads();
                    }
                }
                const bool vn = (pn < 4) ? val0 : val1;
                if (vn) {
                    const float* s = (pn < 4) ? src0 : src1;
                    size_t st = (pn < 4) ? strd0 : strd1;
                    issue_phase(bufs[pn & 1], s, st, (pn & 3) * 128, tid);
                }
                cp_commit();
            }
            const bool vp = (p < 4) ? val0 : val1;
            if (vp) {
                int wb = ((p < 4) ? wb0 : wb1) + (p & 3) * 128;
                mma_phase(acc, bufs[p & 1], sW, wb, w, gi, ti);
            }
        }
        __syncthreads();   // all warps done with stage bufs before partials overwrite

        // Write K-split partials
#pragma unroll
        for (int mt = 0; mt < 4; mt++) {
#pragma unroll
            for (int nt = 0; nt < 4; nt++) {
                int m = mt * 16 + gi;
                int n = nt * 8 + 2 * ti;
                int base = (w * 64 + m) * PPITCH + n;
                sP[base]     = acc[mt][nt][0];
                sP[base + 1] = acc[mt][nt][1];
                sP[base + 8 * PPITCH]     = acc[mt][nt][2];
                sP[base + 8 * PPITCH + 1] = acc[mt][nt][3];
            }
        }
        __syncthreads();

        // Reduce partials + bias + gate math + state update
        float* h_out;
        if (layer == 0)
            h_out = g_hseq + (size_t)t * BH;
        else
            h_out = (t == T_LEN - 1) ? out : (g_h2 + (size_t)(t & 1) * BH);
        const bool final_raw = (layer == 1) && (t == T_LEN - 1);

#pragma unroll
        for (int qq = 0; qq < 2; qq++) {
            int q = tid + (qq << 8);
            int b = q >> 3, j = q & 7;
            float s0 = 0.f, s1 = 0.f, s2 = 0.f, s3 = 0.f;
#pragma unroll
            for (int pw = 0; pw < 8; pw++) {
                int rb = (pw * 64 + b) * PPITCH + j * 4;
                s0 += sP[rb];
                s1 += sP[rb + 1];
                s2 += sP[rb + 2];
                s3 += sP[rb + 3];
            }
            float fg = fsig(s0 + sBias[j * 4 + 0]);
            float ig = fsig(s1 + sBias[j * 4 + 1]);
            float gg = ftanh(s2 + sBias[j * 4 + 2]);
            float og = fsig(s3 + sBias[j * 4 + 3]);
            float c = sC[b * 8 + j];
            c = fg * c + ig * gg;
            sC[b * 8 + j] = c;
            float hv = og * ftanh(c);
            h_out[(size_t)b * HID + (n_blk >> 2) + j] = final_raw ? hv : tfr(hv);
        }

        // Publish: every thread fences its stores, then one atomic bump
        __threadfence();
        __syncthreads();
        if (tid == 0) {
            if (layer == 0) atomicAdd(&g_cnt0[t], 1u);
            else            atomicAdd(&g_cnt1[t], 1u);
        }
    }
}

// ---------------------------------------------------------------------------
// Startup kernels
// ---------------------------------------------------------------------------
__global__ void round_x(const float4* __restrict__ x) {
    size_t i = (size_t)blockIdx.x * blockDim.x + threadIdx.x;
    float4 v = x[i];
    v.x = tfr(v.x); v.y = tfr(v.y); v.z = tfr(v.z); v.w = tfr(v.w);
    ((float4*)g_xr)[i] = v;
}

__global__ void reset_cnt() {
    int i = blockIdx.x * blockDim.x + threadIdx.x;
    if (i < T_LEN) { g_cnt0[i] = 0; g_cnt1[i] = 0; }
}

// ---------------------------------------------------------------------------
// Launch: 3 graph nodes
// ---------------------------------------------------------------------------
extern "C" void kernel_launch(void* const* d_in, const int* in_sizes, int n_in,
                              void* d_out, int out_size) {
    const float* x   = (const float*)d_in[0];
    const float* Wx0 = (const float*)d_in[1];
    const float* bx0 = (const float*)d_in[2];
    const float* Wh0 = (const float*)d_in[3];
    const float* bh0 = (const float*)d_in[4];
    const float* Wx1 = (const float*)d_in[5];
    const float* bx1 = (const float*)d_in[6];
    const float* Wh1 = (const float*)d_in[7];
    const float* bh1 = (const float*)d_in[8];

    const size_t SMEM_BYTES = (size_t)(32 * WPITCH + 2 * SSIZE + 512 + 32) * sizeof(float);
    cudaFuncSetAttribute(lstm_fused, cudaFuncAttributeMaxDynamicSharedMemorySize,
                         (int)SMEM_BYTES);

    round_x<<<4096, 1024>>>((const float4*)x);   // 16M floats / 4 per thread
    reset_cnt<<<2, 256>>>();
    lstm_fused<<<128, 256, SMEM_BYTES>>>(Wx0, bx0, Wh0, bh0,
                                         Wx1, bx1, Wh1, bh1, (float*)d_out);
}

// round 5
// speedup vs baseline: 2.8573x; 1.1527x over previous
#include <cuda_runtime.h>
#include <math.h>

#define T_LEN 512
#define BATCH 64
#define HID   512
#define BH    (BATCH * HID)
#define WPITCH 1036            // weight pitch: mod 32 = 12 -> conflict-free B-frag LDS
#define BPITCH 20              // stage pitch: mod 32 = 20 -> conflict-free A-frag LDS
#define BUFSZ  (64 * BPITCH)   // 1280 floats per chunk buffer
#define PPITCH 33              // partials pitch

// ---------------------------------------------------------------------------
// Static device scratch
// ---------------------------------------------------------------------------
__device__ float g_xr[(size_t)BATCH * T_LEN * HID];     // tf32-rounded x
__device__ float g_hseq[(size_t)T_LEN * BH];            // layer-0 hidden sequence (tf32)
__device__ float g_h2[2 * BH];                          // layer-1 hidden double buffer (tf32)
__device__ unsigned g_cnt0[T_LEN];                      // layer-0 step counters
__device__ unsigned g_cnt1[T_LEN];                      // layer-1 step counters

// ---------------------------------------------------------------------------
// TF32 + MMA helpers
// ---------------------------------------------------------------------------
__device__ __forceinline__ unsigned f2tf(float f) {
    unsigned u;
    asm("cvt.rna.tf32.f32 %0, %1;" : "=r"(u) : "f"(f));
    return u;
}
__device__ __forceinline__ float tfr(float f) { return __uint_as_float(f2tf(f)); }

__device__ __forceinline__ void mma_m16n8k8(float c[4], const unsigned a[4], const unsigned b[2]) {
    asm volatile(
        "mma.sync.aligned.m16n8k8.row.col.f32.tf32.tf32.f32 "
        "{%0,%1,%2,%3}, {%4,%5,%6,%7}, {%8,%9}, {%0,%1,%2,%3};"
        : "+f"(c[0]), "+f"(c[1]), "+f"(c[2]), "+f"(c[3])
        : "r"(a[0]), "r"(a[1]), "r"(a[2]), "r"(a[3]), "r"(b[0]), "r"(b[1]));
}

// Gate-interleaved column n = 4*j + gate -> original weight row r = gate*512 + j
__device__ __forceinline__ int remap_row(int n) { return ((n & 3) << 9) | (n >> 2); }

__device__ __forceinline__ void cp_commit() {
    asm volatile("cp.async.commit_group;" ::: "memory");
}
__device__ __forceinline__ void cp_wait1() {
    asm volatile("cp.async.wait_group 1;" ::: "memory");
}
__device__ __forceinline__ void cp_wait0() {
    asm volatile("cp.async.wait_group 0;" ::: "memory");
}

// Per-warp acquire spin: proceed once *p >= v.
__device__ __forceinline__ void spin_ge(unsigned* p, unsigned v) {
    if ((threadIdx.x & 31) == 0) {
        unsigned x;
        do {
            asm volatile("ld.global.acquire.gpu.u32 %0, [%1];" : "=r"(x) : "l"(p));
        } while (x < v);
    }
    __syncwarp();
}

// Issue one warp-private 64x16 chunk (64 rows x 64 B) via cp.async.cg.
__device__ __forceinline__ void issue_chunk(float* buf, const float* __restrict__ src,
                                            size_t stride, int col0, int lane) {
#pragma unroll
    for (int i = 0; i < 8; i++) {
        int cc = lane + (i << 5);
        int row = cc >> 2, c4 = (cc & 3) << 2;
        const float* g = src + (size_t)row * stride + col0 + c4;
        unsigned s = (unsigned)__cvta_generic_to_shared(buf + row * BPITCH + c4);
        asm volatile("cp.async.cg.shared.global [%0], [%1], 16;" :: "r"(s), "l"(g));
    }
}

// MMA over one 16-wide K chunk: 2 kc x 4 mt x 4 nt m16n8k8.
__device__ __forceinline__ void mma_chunk(float acc[4][4][4], const float* buf,
                                          const float* sW, int wcol, int gi, int ti) {
#pragma unroll
    for (int kc = 0; kc < 2; kc++) {
        int kl = kc << 3;
        unsigned afr[4][4];
#pragma unroll
        for (int mt = 0; mt < 4; mt++) {
            int r = mt * 16;
            afr[mt][0] = __float_as_uint(buf[(r + gi) * BPITCH + kl + ti]);
            afr[mt][1] = __float_as_uint(buf[(r + gi + 8) * BPITCH + kl + ti]);
            afr[mt][2] = __float_as_uint(buf[(r + gi) * BPITCH + kl + ti + 4]);
            afr[mt][3] = __float_as_uint(buf[(r + gi + 8) * BPITCH + kl + ti + 4]);
        }
#pragma unroll
        for (int nt = 0; nt < 4; nt++) {
            unsigned bfr[2];
            bfr[0] = __float_as_uint(sW[(nt * 8 + gi) * WPITCH + wcol + kl + ti]);
            bfr[1] = __float_as_uint(sW[(nt * 8 + gi) * WPITCH + wcol + kl + ti + 4]);
#pragma unroll
            for (int mt = 0; mt < 4; mt++) mma_m16n8k8(acc[mt][nt], afr[mt], bfr);
        }
    }
}

__device__ __forceinline__ float fsig(float x) {
    return __fdividef(1.f, 1.f + __expf(-x));
}
__device__ __forceinline__ float ftanh(float x) {
    return 1.f - __fdividef(2.f, __expf(2.f * x) + 1.f);
}

// ---------------------------------------------------------------------------
// Fused dual-layer persistent LSTM; warp-private cp.async chunk pipeline.
// 128 blocks (64/layer), 256 threads (8 warps). Block owns 32 interleaved
// gate cols; concatenated weights [Wx|Wh] (32x1024 tf32) resident in SMEM.
// Warp w owns K-slice [64w,64w+64) of each 512-wide operand, staged as 4
// chunks of 16-K through a private double buffer. No block syncs in GEMM.
// ---------------------------------------------------------------------------
extern "C" __global__ void __launch_bounds__(256, 1)
lstm_fused(const float* __restrict__ Wx0, const float* __restrict__ bx0,
           const float* __restrict__ Wh0, const float* __restrict__ bh0,
           const float* __restrict__ Wx1, const float* __restrict__ bx1,
           const float* __restrict__ Wh1, const float* __restrict__ bh1,
           float* __restrict__ out) {
    extern __shared__ float smem[];
    float* sW = smem;                          // 32*WPITCH = 33152 floats
    float* sStage = smem + 32 * WPITCH;        // 8 warps * 2 * BUFSZ = 20480 floats
    float* sC = sStage + 8 * 2 * BUFSZ;        // 512
    float* sBias = sC + 512;                   // 32
    float* sP = sStage;                        // partials alias (needs 16896 <= 20480)

    const int tid = threadIdx.x;
    const int w = tid >> 5;
    const int lane = tid & 31;
    const int gi = lane >> 2;
    const int ti = lane & 3;
    const int layer = blockIdx.x >> 6;
    const int bslot = blockIdx.x & 63;
    const int n_blk = bslot * 32;
    const int kw = w * 64;                     // warp K-slice base within an operand

    float* buf0 = sStage + (w * 2) * BUFSZ;
    float* buf1 = buf0 + BUFSZ;

    const float* Wx = layer ? Wx1 : Wx0;
    const float* Wh = layer ? Wh1 : Wh0;
    const float* bxp = layer ? bx1 : bx0;
    const float* bhp = layer ? bh1 : bh0;

    // Stage concatenated weights [Wx | Wh] once (remapped rows, tf32-rounded)
    for (int v = tid; v < 32 * 128; v += 256) {
        int row = v >> 7, c4 = (v & 127) * 4;
        int r = remap_row(n_blk + row);
        float4 fx = *(const float4*)(Wx + (size_t)r * 512 + c4);
        float4 fh = *(const float4*)(Wh + (size_t)r * 512 + c4);
        float* dx = sW + (size_t)row * WPITCH + c4;
        dx[0] = tfr(fx.x); dx[1] = tfr(fx.y); dx[2] = tfr(fx.z); dx[3] = tfr(fx.w);
        float* dh = dx + 512;
        dh[0] = tfr(fh.x); dh[1] = tfr(fh.y); dh[2] = tfr(fh.z); dh[3] = tfr(fh.w);
    }
    if (tid < 32) {
        int r = remap_row(n_blk + tid);
        sBias[tid] = bxp[r] + bhp[r];
    }
    for (int v = tid; v < 512; v += 256) sC[v] = 0.f;
    __syncthreads();

    for (int t = 0; t < T_LEN; t++) {
        float acc[4][4][4];
#pragma unroll
        for (int a = 0; a < 4; a++)
#pragma unroll
            for (int b = 0; b < 4; b++)
#pragma unroll
                for (int c = 0; c < 4; c++) acc[a][b][c] = 0.f;

        const float* srcs[2];
        size_t strds[2];
        int wbs[2];
        bool vals[2];
        if (layer == 0) {
            srcs[0] = g_xr + (size_t)t * 512;            // x[b][t][:]
            strds[0] = (size_t)T_LEN * HID;  wbs[0] = 0;    vals[0] = true;
            srcs[1] = g_hseq + (size_t)(t - 1) * BH;
            strds[1] = HID;                  wbs[1] = 512;  vals[1] = (t > 0);
        } else {
            srcs[0] = g_h2 + (size_t)((t + 1) & 1) * BH;
            strds[0] = HID;                  wbs[0] = 512;  vals[0] = (t > 0);
            srcs[1] = g_hseq + (size_t)t * BH;
            strds[1] = HID;                  wbs[1] = 0;    vals[1] = true;
        }

        // op0 dependency (layer 1: own cohort previous step)
        if (layer == 1 && t > 0) spin_ge(&g_cnt1[t - 1], 64u);

        // Pre-issue chunks 0,1 (always commit to keep group counts aligned)
        if (vals[0]) issue_chunk(buf0, srcs[0], strds[0], kw + 0, lane);
        cp_commit();
        if (vals[0]) issue_chunk(buf1, srcs[0], strds[0], kw + 16, lane);
        cp_commit();

#pragma unroll
        for (int g = 0; g < 8; g++) {
            if (g == 7) cp_wait0(); else cp_wait1();
            const int op = g >> 2;
            if (vals[op])
                mma_chunk(acc, (g & 1) ? buf1 : buf0, sW,
                          wbs[op] + kw + 16 * (g & 3), gi, ti);
            const int gn = g + 2;
            if (gn < 8) {
                if (gn == 4) {   // op1 dependency (h1 for both layers)
                    if (layer == 0) {
                        if (t > 0) spin_ge(&g_cnt0[t - 1], 64u);
                    } else {
                        spin_ge(&g_cnt0[t], 64u);
                    }
                }
                const int opn = gn >> 2;
                if (vals[opn])
                    issue_chunk((gn & 1) ? buf1 : buf0, srcs[opn], strds[opn],
                                kw + 16 * (gn & 3), lane);
                cp_commit();
            }
        }

        __syncthreads();   // all warps done with stage bufs before partials alias

        // Write K-split partials
#pragma unroll
        for (int mt = 0; mt < 4; mt++) {
#pragma unroll
            for (int nt = 0; nt < 4; nt++) {
                int m = mt * 16 + gi;
                int n = nt * 8 + 2 * ti;
                int base = (w * 64 + m) * PPITCH + n;
                sP[base]     = acc[mt][nt][0];
                sP[base + 1] = acc[mt][nt][1];
                sP[base + 8 * PPITCH]     = acc[mt][nt][2];
                sP[base + 8 * PPITCH + 1] = acc[mt][nt][3];
            }
        }
        __syncthreads();

        // Reduce partials + bias + gate math + state update
        float* h_out;
        if (layer == 0)
            h_out = g_hseq + (size_t)t * BH;
        else
            h_out = (t == T_LEN - 1) ? out : (g_h2 + (size_t)(t & 1) * BH);
        const bool final_raw = (layer == 1) && (t == T_LEN - 1);

#pragma unroll
        for (int qq = 0; qq < 2; qq++) {
            int q = tid + (qq << 8);
            int b = q >> 3, j = q & 7;
            float s0 = 0.f, s1 = 0.f, s2 = 0.f, s3 = 0.f;
#pragma unroll
            for (int pw = 0; pw < 8; pw++) {
                int rb = (pw * 64 + b) * PPITCH + j * 4;
                s0 += sP[rb];
                s1 += sP[rb + 1];
                s2 += sP[rb + 2];
                s3 += sP[rb + 3];
            }
            float fg = fsig(s0 + sBias[j * 4 + 0]);
            float ig = fsig(s1 + sBias[j * 4 + 1]);
            float gg = ftanh(s2 + sBias[j * 4 + 2]);
            float og = fsig(s3 + sBias[j * 4 + 3]);
            float c = sC[b * 8 + j];
            c = fg * c + ig * gg;
            sC[b * 8 + j] = c;
            float hv = og * ftanh(c);
            h_out[(size_t)b * HID + (n_blk >> 2) + j] = final_raw ? hv : tfr(hv);
        }

        // Publish: fence own stores, block-sync, one flag bump
        __threadfence();
        __syncthreads();
        if (tid == 0) {
            if (layer == 0) atomicAdd(&g_cnt0[t], 1u);
            else            atomicAdd(&g_cnt1[t], 1u);
        }
    }
}

// ---------------------------------------------------------------------------
// Startup kernels
// ---------------------------------------------------------------------------
__global__ void round_x(const float4* __restrict__ x) {
    size_t i = (size_t)blockIdx.x * blockDim.x + threadIdx.x;
    float4 v = x[i];
    v.x = tfr(v.x); v.y = tfr(v.y); v.z = tfr(v.z); v.w = tfr(v.w);
    ((float4*)g_xr)[i] = v;
}

__global__ void reset_cnt() {
    int i = blockIdx.x * blockDim.x + threadIdx.x;
    if (i < T_LEN) { g_cnt0[i] = 0; g_cnt1[i] = 0; }
}

// ---------------------------------------------------------------------------
// Launch: 3 graph nodes
// ---------------------------------------------------------------------------
extern "C" void kernel_launch(void* const* d_in, const int* in_sizes, int n_in,
                              void* d_out, int out_size) {
    const float* x   = (const float*)d_in[0];
    const float* Wx0 = (const float*)d_in[1];
    const float* bx0 = (const float*)d_in[2];
    const float* Wh0 = (const float*)d_in[3];
    const float* bh0 = (const float*)d_in[4];
    const float* Wx1 = (const float*)d_in[5];
    const float* bx1 = (const float*)d_in[6];
    const float* Wh1 = (const float*)d_in[7];
    const float* bh1 = (const float*)d_in[8];

    const size_t SMEM_BYTES =
        (size_t)(32 * WPITCH + 8 * 2 * BUFSZ + 512 + 32) * sizeof(float);
    cudaFuncSetAttribute(lstm_fused, cudaFuncAttributeMaxDynamicSharedMemorySize,
                         (int)SMEM_BYTES);

    round_x<<<4096, 1024>>>((const float4*)x);
    reset_cnt<<<2, 256>>>();
    lstm_fused<<<128, 256, SMEM_BYTES>>>(Wx0, bx0, Wh0, bh0,
                                         Wx1, bx1, Wh1, bh1, (float*)d_out);
}

// round 6
// speedup vs baseline: 2.8789x; 1.0075x over previous
#include <cuda_runtime.h>
#include <math.h>

#define T_LEN 512
#define BATCH 64
#define HID   512
#define BH    (BATCH * HID)
#define WPITCH0 516            // op0 weight pitch: mod 32 = 4 -> conflict-free B-frag LDS
#define BPITCH 20              // stage pitch: mod 32 = 20 -> conflict-free A-frag LDS
#define BUFSZ  (64 * BPITCH)   // 1280 floats per chunk buffer
#define NBUF   3               // staging depth per warp
#define PPITCH 33              // partials pitch

// ---------------------------------------------------------------------------
// Static device scratch
// ---------------------------------------------------------------------------
__device__ float g_xr[(size_t)BATCH * T_LEN * HID];     // tf32-rounded x
__device__ float g_hseq[(size_t)T_LEN * BH];            // layer-0 hidden sequence (tf32)
__device__ float g_h2[2 * BH];                          // layer-1 hidden double buffer (tf32)
__device__ unsigned g_cnt0[T_LEN];                      // layer-0 step counters
__device__ unsigned g_cnt1[T_LEN];                      // layer-1 step counters

// ---------------------------------------------------------------------------
// TF32 + MMA helpers
// ---------------------------------------------------------------------------
__device__ __forceinline__ unsigned f2tf(float f) {
    unsigned u;
    asm("cvt.rna.tf32.f32 %0, %1;" : "=r"(u) : "f"(f));
    return u;
}
__device__ __forceinline__ float tfr(float f) { return __uint_as_float(f2tf(f)); }

__device__ __forceinline__ void mma_m16n8k8(float c[4], const unsigned a[4], const unsigned b[2]) {
    asm volatile(
        "mma.sync.aligned.m16n8k8.row.col.f32.tf32.tf32.f32 "
        "{%0,%1,%2,%3}, {%4,%5,%6,%7}, {%8,%9}, {%0,%1,%2,%3};"
        : "+f"(c[0]), "+f"(c[1]), "+f"(c[2]), "+f"(c[3])
        : "r"(a[0]), "r"(a[1]), "r"(a[2]), "r"(a[3]), "r"(b[0]), "r"(b[1]));
}

// Gate-interleaved column n = 4*j + gate -> original weight row r = gate*512 + j
__device__ __forceinline__ int remap_row(int n) { return ((n & 3) << 9) | (n >> 2); }

__device__ __forceinline__ void cp_commit() {
    asm volatile("cp.async.commit_group;" ::: "memory");
}
__device__ __forceinline__ void cp_wait0() { asm volatile("cp.async.wait_group 0;" ::: "memory"); }
__device__ __forceinline__ void cp_wait1() { asm volatile("cp.async.wait_group 1;" ::: "memory"); }
__device__ __forceinline__ void cp_wait2() { asm volatile("cp.async.wait_group 2;" ::: "memory"); }

// Per-warp acquire spin: proceed once *p >= v.
__device__ __forceinline__ void spin_ge(unsigned* p, unsigned v) {
    if ((threadIdx.x & 31) == 0) {
        unsigned x;
        do {
            asm volatile("ld.global.acquire.gpu.u32 %0, [%1];" : "=r"(x) : "l"(p));
        } while (x < v);
    }
    __syncwarp();
}

// Issue one warp-private 64x16 chunk (64 rows x 64 B) via cp.async.cg.
__device__ __forceinline__ void issue_chunk(float* buf, const float* __restrict__ src,
                                            size_t stride, int col0, int lane) {
#pragma unroll
    for (int i = 0; i < 8; i++) {
        int cc = lane + (i << 5);
        int row = cc >> 2, c4 = (cc & 3) << 2;
        const float* g = src + (size_t)row * stride + col0 + c4;
        unsigned s = (unsigned)__cvta_generic_to_shared(buf + row * BPITCH + c4);
        asm volatile("cp.async.cg.shared.global [%0], [%1], 16;" :: "r"(s), "l"(g));
    }
}

// MMA over one 16-wide K chunk with B from SMEM (op0 path).
__device__ __forceinline__ void mma_chunk_smemB(float acc[4][4][4], const float* buf,
                                                const float* sW0, int kbase,
                                                int gi, int ti) {
#pragma unroll
    for (int kc = 0; kc < 2; kc++) {
        int kl = kc << 3;
        unsigned afr[4][4];
#pragma unroll
        for (int mt = 0; mt < 4; mt++) {
            int r = mt * 16;
            afr[mt][0] = __float_as_uint(buf[(r + gi) * BPITCH + kl + ti]);
            afr[mt][1] = __float_as_uint(buf[(r + gi + 8) * BPITCH + kl + ti]);
            afr[mt][2] = __float_as_uint(buf[(r + gi) * BPITCH + kl + ti + 4]);
            afr[mt][3] = __float_as_uint(buf[(r + gi + 8) * BPITCH + kl + ti + 4]);
        }
#pragma unroll
        for (int nt = 0; nt < 4; nt++) {
            unsigned bfr[2];
            bfr[0] = __float_as_uint(sW0[(nt * 8 + gi) * WPITCH0 + kbase + kl + ti]);
            bfr[1] = __float_as_uint(sW0[(nt * 8 + gi) * WPITCH0 + kbase + kl + ti + 4]);
#pragma unroll
            for (int mt = 0; mt < 4; mt++) mma_m16n8k8(acc[mt][nt], afr[mt], bfr);
        }
    }
}

// MMA over one 16-wide K chunk with B from registers (op1 / critical path).
__device__ __forceinline__ void mma_chunk_regB(float acc[4][4][4], const float* buf,
                                               const unsigned breg[4][8][2], int cidx,
                                               int gi, int ti) {
#pragma unroll
    for (int kc = 0; kc < 2; kc++) {
        int kl = kc << 3;
        int kk = (cidx << 1) + kc;
        unsigned afr[4][4];
#pragma unroll
        for (int mt = 0; mt < 4; mt++) {
            int r = mt * 16;
            afr[mt][0] = __float_as_uint(buf[(r + gi) * BPITCH + kl + ti]);
            afr[mt][1] = __float_as_uint(buf[(r + gi + 8) * BPITCH + kl + ti]);
            afr[mt][2] = __float_as_uint(buf[(r + gi) * BPITCH + kl + ti + 4]);
            afr[mt][3] = __float_as_uint(buf[(r + gi + 8) * BPITCH + kl + ti + 4]);
        }
#pragma unroll
        for (int nt = 0; nt < 4; nt++)
#pragma unroll
            for (int mt = 0; mt < 4; mt++)
                mma_m16n8k8(acc[mt][nt], afr[mt], breg[nt][kk]);
    }
}

__device__ __forceinline__ float fsig(float x) {
    return __fdividef(1.f, 1.f + __expf(-x));
}
__device__ __forceinline__ float ftanh(float x) {
    return 1.f - __fdividef(2.f, __expf(2.f * x) + 1.f);
}

// ---------------------------------------------------------------------------
// Fused dual-layer persistent LSTM.
// 128 blocks (64/layer), 256 threads (8 warps). Block owns 32 interleaved
// gate cols. op1 (spin-gated recurrent operand) weights live in REGISTERS
// (64 u32/thread, preloaded once); op0 weights in SMEM. Warp-private
// cp.async staging, depth 3.
// ---------------------------------------------------------------------------
extern "C" __global__ void __launch_bounds__(256, 1)
lstm_fused(const float* __restrict__ Wx0, const float* __restrict__ bx0,
           const float* __restrict__ Wh0, const float* __restrict__ bh0,
           const float* __restrict__ Wx1, const float* __restrict__ bx1,
           const float* __restrict__ Wh1, const float* __restrict__ bh1,
           float* __restrict__ out) {
    extern __shared__ float smem[];
    float* sW0 = smem;                          // 32*WPITCH0 = 16512 floats
    float* sStage = smem + 32 * WPITCH0;        // 8*NBUF*BUFSZ = 30720 floats
    float* sC = sStage + 8 * NBUF * BUFSZ;      // 512
    float* sBias = sC + 512;                    // 32
    float* sP = sStage;                         // partials alias (16896 <= 30720)

    const int tid = threadIdx.x;
    const int w = tid >> 5;
    const int lane = tid & 31;
    const int gi = lane >> 2;
    const int ti = lane & 3;
    const int layer = blockIdx.x >> 6;
    const int bslot = blockIdx.x & 63;
    const int n_blk = bslot * 32;
    const int kw = w * 64;                      // warp K-slice base within an operand

    float* bufs[NBUF];
#pragma unroll
    for (int i = 0; i < NBUF; i++) bufs[i] = sStage + (w * NBUF + i) * BUFSZ;

    // op0 weight matrix -> SMEM ; op1 weight matrix -> registers
    const float* W0 = layer ? Wh1 : Wx0;   // op0: L0=x·Wx0, L1=h2·Wh1
    const float* W1 = layer ? Wx1 : Wh0;   // op1: L0=h1·Wh0, L1=h1·Wx1
    const float* bxp = layer ? bx1 : bx0;
    const float* bhp = layer ? bh1 : bh0;

    // Stage op0 weights once (remapped rows, tf32-rounded)
    for (int v = tid; v < 32 * 128; v += 256) {
        int row = v >> 7, c4 = (v & 127) * 4;
        int r = remap_row(n_blk + row);
        float4 f = *(const float4*)(W0 + (size_t)r * 512 + c4);
        float* d = sW0 + (size_t)row * WPITCH0 + c4;
        d[0] = tfr(f.x); d[1] = tfr(f.y); d[2] = tfr(f.z); d[3] = tfr(f.w);
    }
    if (tid < 32) {
        int r = remap_row(n_blk + tid);
        sBias[tid] = bxp[r] + bhp[r];
    }
    for (int v = tid; v < 512; v += 256) sC[v] = 0.f;

    // Preload op1 B-fragments into registers (constant across all steps)
    unsigned breg[4][8][2];
#pragma unroll
    for (int nt = 0; nt < 4; nt++) {
        int r = remap_row(n_blk + nt * 8 + gi);
        const float* wr = W1 + (size_t)r * 512 + kw + ti;
#pragma unroll
        for (int kc = 0; kc < 8; kc++) {
            breg[nt][kc][0] = f2tf(wr[kc * 8]);
            breg[nt][kc][1] = f2tf(wr[kc * 8 + 4]);
        }
    }
    __syncthreads();

    for (int t = 0; t < T_LEN; t++) {
        float acc[4][4][4];
#pragma unroll
        for (int a = 0; a < 4; a++)
#pragma unroll
            for (int b = 0; b < 4; b++)
#pragma unroll
                for (int c = 0; c < 4; c++) acc[a][b][c] = 0.f;

        const float* srcs[2];
        size_t strds[2];
        bool vals[2];
        if (layer == 0) {
            srcs[0] = g_xr + (size_t)t * 512;            // x[b][t][:]
            strds[0] = (size_t)T_LEN * HID;  vals[0] = true;
            srcs[1] = g_hseq + (size_t)(t - 1) * BH;
            strds[1] = HID;                  vals[1] = (t > 0);
        } else {
            srcs[0] = g_h2 + (size_t)((t + 1) & 1) * BH;
            strds[0] = HID;                  vals[0] = (t > 0);
            srcs[1] = g_hseq + (size_t)t * BH;
            strds[1] = HID;                  vals[1] = true;
        }

        // op0 dependency (layer 1: own cohort previous step)
        if (layer == 1 && t > 0) spin_ge(&g_cnt1[t - 1], 64u);

        // Pre-issue op0 chunks 0..2 (always commit to keep group counts aligned)
#pragma unroll
        for (int c = 0; c < 3; c++) {
            if (vals[0]) issue_chunk(bufs[c], srcs[0], strds[0], kw + 16 * c, lane);
            cp_commit();
        }

#pragma unroll
        for (int g = 0; g < 8; g++) {
            if (g < 6) cp_wait2(); else if (g == 6) cp_wait1(); else cp_wait0();
            const int op = g >> 2;
            if (vals[op]) {
                if (op == 0)
                    mma_chunk_smemB(acc, bufs[g % NBUF], sW0, kw + 16 * (g & 3), gi, ti);
                else
                    mma_chunk_regB(acc, bufs[g % NBUF], breg, g & 3, gi, ti);
            }
            const int gn = g + 3;
            if (gn < 8) {
                if (gn == 4) {   // op1 dependency (h1 for L0-own / L0->L1)
                    if (layer == 0) {
                        if (t > 0) spin_ge(&g_cnt0[t - 1], 64u);
                    } else {
                        spin_ge(&g_cnt0[t], 64u);
                    }
                }
                const int opn = gn >> 2;
                if (vals[opn])
                    issue_chunk(bufs[gn % NBUF], srcs[opn], strds[opn],
                                kw + 16 * (gn & 3), lane);
                cp_commit();
            }
        }

        __syncthreads();   // all warps done with stage bufs before partials alias

        // Write K-split partials
#pragma unroll
        for (int mt = 0; mt < 4; mt++) {
#pragma unroll
            for (int nt = 0; nt < 4; nt++) {
                int m = mt * 16 + gi;
                int n = nt * 8 + 2 * ti;
                int base = (w * 64 + m) * PPITCH + n;
                sP[base]     = acc[mt][nt][0];
                sP[base + 1] = acc[mt][nt][1];
                sP[base + 8 * PPITCH]     = acc[mt][nt][2];
                sP[base + 8 * PPITCH + 1] = acc[mt][nt][3];
            }
        }
        __syncthreads();

        // Reduce partials + bias + gate math + state update
        float* h_out;
        if (layer == 0)
            h_out = g_hseq + (size_t)t * BH;
        else
            h_out = (t == T_LEN - 1) ? out : (g_h2 + (size_t)(t & 1) * BH);
        const bool final_raw = (layer == 1) && (t == T_LEN - 1);

#pragma unroll
        for (int qq = 0; qq < 2; qq++) {
            int q = tid + (qq << 8);
            int b = q >> 3, j = q & 7;
            float s0 = 0.f, s1 = 0.f, s2 = 0.f, s3 = 0.f;
#pragma unroll
            for (int pw = 0; pw < 8; pw++) {
                int rb = (pw * 64 + b) * PPITCH + j * 4;
                s0 += sP[rb];
                s1 += sP[rb + 1];
                s2 += sP[rb + 2];
                s3 += sP[rb + 3];
            }
            float fg = fsig(s0 + sBias[j * 4 + 0]);
            float ig = fsig(s1 + sBias[j * 4 + 1]);
            float gg = ftanh(s2 + sBias[j * 4 + 2]);
            float og = fsig(s3 + sBias[j * 4 + 3]);
            float c = sC[b * 8 + j];
            c = fg * c + ig * gg;
            sC[b * 8 + j] = c;
            float hv = og * ftanh(c);
            h_out[(size_t)b * HID + (n_blk >> 2) + j] = final_raw ? hv : tfr(hv);
        }

        // Publish: fence own stores, block-sync, one flag bump
        __threadfence();
        __syncthreads();
        if (tid == 0) {
            if (layer == 0) atomicAdd(&g_cnt0[t], 1u);
            else            atomicAdd(&g_cnt1[t], 1u);
        }
    }
}

// ---------------------------------------------------------------------------
// Startup kernels
// ---------------------------------------------------------------------------
__global__ void round_x(const float4* __restrict__ x) {
    size_t i = (size_t)blockIdx.x * blockDim.x + threadIdx.x;
    float4 v = x[i];
    v.x = tfr(v.x); v.y = tfr(v.y); v.z = tfr(v.z); v.w = tfr(v.w);
    ((float4*)g_xr)[i] = v;
}

__global__ void reset_cnt() {
    int i = blockIdx.x * blockDim.x + threadIdx.x;
    if (i < T_LEN) { g_cnt0[i] = 0; g_cnt1[i] = 0; }
}

// ---------------------------------------------------------------------------
// Launch: 3 graph nodes
// ---------------------------------------------------------------------------
extern "C" void kernel_launch(void* const* d_in, const int* in_sizes, int n_in,
                              void* d_out, int out_size) {
    const float* x   = (const float*)d_in[0];
    const float* Wx0 = (const float*)d_in[1];
    const float* bx0 = (const float*)d_in[2];
    const float* Wh0 = (const float*)d_in[3];
    const float* bh0 = (const float*)d_in[4];
    const float* Wx1 = (const float*)d_in[5];
    const float* bx1 = (const float*)d_in[6];
    const float* Wh1 = (const float*)d_in[7];
    const float* bh1 = (const float*)d_in[8];

    const size_t SMEM_BYTES =
        (size_t)(32 * WPITCH0 + 8 * NBUF * BUFSZ + 512 + 32) * sizeof(float);
    cudaFuncSetAttribute(lstm_fused, cudaFuncAttributeMaxDynamicSharedMemorySize,
                         (int)SMEM_BYTES);

    round_x<<<4096, 1024>>>((const float4*)x);
    reset_cnt<<<2, 256>>>();
    lstm_fused<<<128, 256, SMEM_BYTES>>>(Wx0, bx0, Wh0, bh0,
                                         Wx1, bx1, Wh1, bh1, (float*)d_out);
}

// round 7
// speedup vs baseline: 3.1103x; 1.0804x over previous
#include <cuda_runtime.h>
#include <math.h>

#define T_LEN 512
#define BATCH 64
#define HID   512
#define BH    (BATCH * HID)
#define WPITCH0 516            // op0 weight pitch: mod 32 = 4 -> conflict-free B-frag LDS
#define BPITCH 20              // stage pitch: mod 32 = 20 -> conflict-free A-frag LDS
#define BUFSZ  (64 * BPITCH)   // 1280 floats per chunk buffer
#define NBUF   3               // staging depth per warp
#define PPITCH 33              // partials pitch

// ---------------------------------------------------------------------------
// Static device scratch
// ---------------------------------------------------------------------------
__device__ float g_xr[(size_t)BATCH * T_LEN * HID];     // tf32-rounded x
__device__ float g_hseq[(size_t)T_LEN * BH];            // layer-0 hidden sequence (tf32)
__device__ float g_h2[2 * BH];                          // layer-1 hidden double buffer (tf32)
__device__ unsigned g_cnt[2 * T_LEN * 8];               // per-(layer,step,group) counters

// ---------------------------------------------------------------------------
// TF32 + MMA helpers
// ---------------------------------------------------------------------------
__device__ __forceinline__ unsigned f2tf(float f) {
    unsigned u;
    asm("cvt.rna.tf32.f32 %0, %1;" : "=r"(u) : "f"(f));
    return u;
}
__device__ __forceinline__ float tfr(float f) { return __uint_as_float(f2tf(f)); }

__device__ __forceinline__ void mma_m16n8k8(float c[4], const unsigned a[4], const unsigned b[2]) {
    asm volatile(
        "mma.sync.aligned.m16n8k8.row.col.f32.tf32.tf32.f32 "
        "{%0,%1,%2,%3}, {%4,%5,%6,%7}, {%8,%9}, {%0,%1,%2,%3};"
        : "+f"(c[0]), "+f"(c[1]), "+f"(c[2]), "+f"(c[3])
        : "r"(a[0]), "r"(a[1]), "r"(a[2]), "r"(a[3]), "r"(b[0]), "r"(b[1]));
}

// Gate-interleaved column n = 4*j + gate -> original weight row r = gate*512 + j
__device__ __forceinline__ int remap_row(int n) { return ((n & 3) << 9) | (n >> 2); }

__device__ __forceinline__ void cp_commit() {
    asm volatile("cp.async.commit_group;" ::: "memory");
}
__device__ __forceinline__ void cp_wait0() { asm volatile("cp.async.wait_group 0;" ::: "memory"); }
__device__ __forceinline__ void cp_wait1() { asm volatile("cp.async.wait_group 1;" ::: "memory"); }
__device__ __forceinline__ void cp_wait2() { asm volatile("cp.async.wait_group 2;" ::: "memory"); }

// Per-warp acquire spin: proceed once *p >= v.
__device__ __forceinline__ void spin_ge(unsigned* p, unsigned v) {
    if ((threadIdx.x & 31) == 0) {
        unsigned x;
        do {
            asm volatile("ld.global.acquire.gpu.u32 %0, [%1];" : "=r"(x) : "l"(p));
        } while (x < v);
    }
    __syncwarp();
}

// Issue one warp-private 64x16 chunk (64 rows x 64 B) via cp.async.cg.
__device__ __forceinline__ void issue_chunk(float* buf, const float* __restrict__ src,
                                            size_t stride, int col0, int lane) {
#pragma unroll
    for (int i = 0; i < 8; i++) {
        int cc = lane + (i << 5);
        int row = cc >> 2, c4 = (cc & 3) << 2;
        const float* g = src + (size_t)row * stride + col0 + c4;
        unsigned s = (unsigned)__cvta_generic_to_shared(buf + row * BPITCH + c4);
        asm volatile("cp.async.cg.shared.global [%0], [%1], 16;" :: "r"(s), "l"(g));
    }
}

// MMA over one 16-wide K chunk with B from SMEM (op0 path).
__device__ __forceinline__ void mma_chunk_smemB(float acc[4][4][4], const float* buf,
                                                const float* sW0, int kbase,
                                                int gi, int ti) {
#pragma unroll
    for (int kc = 0; kc < 2; kc++) {
        int kl = kc << 3;
        unsigned afr[4][4];
#pragma unroll
        for (int mt = 0; mt < 4; mt++) {
            int r = mt * 16;
            afr[mt][0] = __float_as_uint(buf[(r + gi) * BPITCH + kl + ti]);
            afr[mt][1] = __float_as_uint(buf[(r + gi + 8) * BPITCH + kl + ti]);
            afr[mt][2] = __float_as_uint(buf[(r + gi) * BPITCH + kl + ti + 4]);
            afr[mt][3] = __float_as_uint(buf[(r + gi + 8) * BPITCH + kl + ti + 4]);
        }
#pragma unroll
        for (int nt = 0; nt < 4; nt++) {
            unsigned bfr[2];
            bfr[0] = __float_as_uint(sW0[(nt * 8 + gi) * WPITCH0 + kbase + kl + ti]);
            bfr[1] = __float_as_uint(sW0[(nt * 8 + gi) * WPITCH0 + kbase + kl + ti + 4]);
#pragma unroll
            for (int mt = 0; mt < 4; mt++) mma_m16n8k8(acc[mt][nt], afr[mt], bfr);
        }
    }
}

// MMA over one 16-wide K chunk with B from registers (op1 / critical path).
__device__ __forceinline__ void mma_chunk_regB(float acc[4][4][4], const float* buf,
                                               const unsigned breg[4][8][2], int cidx,
                                               int gi, int ti) {
#pragma unroll
    for (int kc = 0; kc < 2; kc++) {
        int kl = kc << 3;
        int kk = (cidx << 1) + kc;
        unsigned afr[4][4];
#pragma unroll
        for (int mt = 0; mt < 4; mt++) {
            int r = mt * 16;
            afr[mt][0] = __float_as_uint(buf[(r + gi) * BPITCH + kl + ti]);
            afr[mt][1] = __float_as_uint(buf[(r + gi + 8) * BPITCH + kl + ti]);
            afr[mt][2] = __float_as_uint(buf[(r + gi) * BPITCH + kl + ti + 4]);
            afr[mt][3] = __float_as_uint(buf[(r + gi + 8) * BPITCH + kl + ti + 4]);
        }
#pragma unroll
        for (int nt = 0; nt < 4; nt++)
#pragma unroll
            for (int mt = 0; mt < 4; mt++)
                mma_m16n8k8(acc[mt][nt], afr[mt], breg[nt][kk]);
    }
}

__device__ __forceinline__ float fsig(float x) {
    return __fdividef(1.f, 1.f + __expf(-x));
}
__device__ __forceinline__ float ftanh(float x) {
    return 1.f - __fdividef(2.f, __expf(2.f * x) + 1.f);
}

// ---------------------------------------------------------------------------
// Fused dual-layer persistent LSTM.
// 128 blocks (64/layer), 256 threads (8 warps). Block owns 32 interleaved
// gate cols (8 h-outputs). ALL dependency waits are per-warp, per 8-block
// producer group: warp w's K-slice [64w,64w+64) is produced by blocks
// [8w,8w+8) -> counter g_cnt[layer][t][w]. Publish via red.release.gpu.
// ---------------------------------------------------------------------------
extern "C" __global__ void __launch_bounds__(256, 1)
lstm_fused(const float* __restrict__ Wx0, const float* __restrict__ bx0,
           const float* __restrict__ Wh0, const float* __restrict__ bh0,
           const float* __restrict__ Wx1, const float* __restrict__ bx1,
           const float* __restrict__ Wh1, const float* __restrict__ bh1,
           float* __restrict__ out) {
    extern __shared__ float smem[];
    float* sW0 = smem;                          // 32*WPITCH0 = 16512 floats
    float* sStage = smem + 32 * WPITCH0;        // 8*NBUF*BUFSZ = 30720 floats
    float* sC = sStage + 8 * NBUF * BUFSZ;      // 512
    float* sBias = sC + 512;                    // 32
    float* sP = sStage;                         // partials alias (16896 <= 30720)

    const int tid = threadIdx.x;
    const int w = tid >> 5;
    const int lane = tid & 31;
    const int gi = lane >> 2;
    const int ti = lane & 3;
    const int layer = blockIdx.x >> 6;
    const int bslot = blockIdx.x & 63;
    const int n_blk = bslot * 32;
    const int kw = w * 64;                      // warp K-slice base within an operand

    float* bufs[NBUF];
#pragma unroll
    for (int i = 0; i < NBUF; i++) bufs[i] = sStage + (w * NBUF + i) * BUFSZ;

    // op0 weight matrix -> SMEM ; op1 weight matrix -> registers
    const float* W0 = layer ? Wh1 : Wx0;   // op0: L0=x·Wx0, L1=h2·Wh1
    const float* W1 = layer ? Wx1 : Wh0;   // op1: L0=h1·Wh0, L1=h1·Wx1
    const float* bxp = layer ? bx1 : bx0;
    const float* bhp = layer ? bh1 : bh0;

    // Stage op0 weights once (remapped rows, tf32-rounded)
    for (int v = tid; v < 32 * 128; v += 256) {
        int row = v >> 7, c4 = (v & 127) * 4;
        int r = remap_row(n_blk + row);
        float4 f = *(const float4*)(W0 + (size_t)r * 512 + c4);
        float* d = sW0 + (size_t)row * WPITCH0 + c4;
        d[0] = tfr(f.x); d[1] = tfr(f.y); d[2] = tfr(f.z); d[3] = tfr(f.w);
    }
    if (tid < 32) {
        int r = remap_row(n_blk + tid);
        sBias[tid] = bxp[r] + bhp[r];
    }
    for (int v = tid; v < 512; v += 256) sC[v] = 0.f;

    // Preload op1 B-fragments into registers (constant across all steps)
    unsigned breg[4][8][2];
#pragma unroll
    for (int nt = 0; nt < 4; nt++) {
        int r = remap_row(n_blk + nt * 8 + gi);
        const float* wr = W1 + (size_t)r * 512 + kw + ti;
#pragma unroll
        for (int kc = 0; kc < 8; kc++) {
            breg[nt][kc][0] = f2tf(wr[kc * 8]);
            breg[nt][kc][1] = f2tf(wr[kc * 8 + 4]);
        }
    }
    __syncthreads();

    for (int t = 0; t < T_LEN; t++) {
        float acc[4][4][4];
#pragma unroll
        for (int a = 0; a < 4; a++)
#pragma unroll
            for (int b = 0; b < 4; b++)
#pragma unroll
                for (int c = 0; c < 4; c++) acc[a][b][c] = 0.f;

        const float* srcs[2];
        size_t strds[2];
        bool vals[2];
        if (layer == 0) {
            srcs[0] = g_xr + (size_t)t * 512;            // x[b][t][:]
            strds[0] = (size_t)T_LEN * HID;  vals[0] = true;
            srcs[1] = g_hseq + (size_t)(t - 1) * BH;
            strds[1] = HID;                  vals[1] = (t > 0);
        } else {
            srcs[0] = g_h2 + (size_t)((t + 1) & 1) * BH;
            strds[0] = HID;                  vals[0] = (t > 0);
            srcs[1] = g_hseq + (size_t)t * BH;
            strds[1] = HID;                  vals[1] = true;
        }

        // op0 dependency (layer 1: own cohort, previous step, own group only)
        if (layer == 1 && t > 0)
            spin_ge(&g_cnt[(T_LEN + (t - 1)) * 8 + w], 8u);

        // Pre-issue op0 chunks 0..2 (always commit to keep group counts aligned)
#pragma unroll
        for (int c = 0; c < 3; c++) {
            if (vals[0]) issue_chunk(bufs[c], srcs[0], strds[0], kw + 16 * c, lane);
            cp_commit();
        }

#pragma unroll
        for (int g = 0; g < 8; g++) {
            if (g < 6) cp_wait2(); else if (g == 6) cp_wait1(); else cp_wait0();
            const int op = g >> 2;
            if (vals[op]) {
                if (op == 0)
                    mma_chunk_smemB(acc, bufs[g % NBUF], sW0, kw + 16 * (g & 3), gi, ti);
                else
                    mma_chunk_regB(acc, bufs[g % NBUF], breg, g & 3, gi, ti);
            }
            const int gn = g + 3;
            if (gn < 8) {
                if (gn == 4) {   // op1 dependency (h1), own group only
                    if (layer == 0) {
                        if (t > 0) spin_ge(&g_cnt[(t - 1) * 8 + w], 8u);
                    } else {
                        spin_ge(&g_cnt[t * 8 + w], 8u);
                    }
                }
                const int opn = gn >> 2;
                if (vals[opn])
                    issue_chunk(bufs[gn % NBUF], srcs[opn], strds[opn],
                                kw + 16 * (gn & 3), lane);
                cp_commit();
            }
        }

        __syncthreads();   // all warps done with stage bufs before partials alias

        // Write K-split partials
#pragma unroll
        for (int mt = 0; mt < 4; mt++) {
#pragma unroll
            for (int nt = 0; nt < 4; nt++) {
                int m = mt * 16 + gi;
                int n = nt * 8 + 2 * ti;
                int base = (w * 64 + m) * PPITCH + n;
                sP[base]     = acc[mt][nt][0];
                sP[base + 1] = acc[mt][nt][1];
                sP[base + 8 * PPITCH]     = acc[mt][nt][2];
                sP[base + 8 * PPITCH + 1] = acc[mt][nt][3];
            }
        }
        __syncthreads();

        // Reduce partials + bias + gate math + state update
        float* h_out;
        if (layer == 0)
            h_out = g_hseq + (size_t)t * BH;
        else
            h_out = (t == T_LEN - 1) ? out : (g_h2 + (size_t)(t & 1) * BH);
        const bool final_raw = (layer == 1) && (t == T_LEN - 1);

#pragma unroll
        for (int qq = 0; qq < 2; qq++) {
            int q = tid + (qq << 8);
            int b = q >> 3, j = q & 7;
            float s0 = 0.f, s1 = 0.f, s2 = 0.f, s3 = 0.f;
#pragma unroll
            for (int pw = 0; pw < 8; pw++) {
                int rb = (pw * 64 + b) * PPITCH + j * 4;
                s0 += sP[rb];
                s1 += sP[rb + 1];
                s2 += sP[rb + 2];
                s3 += sP[rb + 3];
            }
            float fg = fsig(s0 + sBias[j * 4 + 0]);
            float ig = fsig(s1 + sBias[j * 4 + 1]);
            float gg = ftanh(s2 + sBias[j * 4 + 2]);
            float og = fsig(s3 + sBias[j * 4 + 3]);
            float c = sC[b * 8 + j];
            c = fg * c + ig * gg;
            sC[b * 8 + j] = c;
            float hv = og * ftanh(c);
            h_out[(size_t)b * HID + (n_blk >> 2) + j] = final_raw ? hv : tfr(hv);
        }

        // Publish: block-sync then ONE release-reduction (CG grid-sync idiom;
        // cumulative release makes all threads' prior stores visible)
        __syncthreads();
        if (tid == 0) {
            unsigned* p = &g_cnt[((layer * T_LEN) + t) * 8 + (bslot >> 3)];
            unsigned one = 1u;
            asm volatile("red.release.gpu.global.add.u32 [%0], %1;"
                         :: "l"(p), "r"(one) : "memory");
        }
    }
}

// ---------------------------------------------------------------------------
// Prep: tf32-round x AND reset counters (one kernel -> 2 graph nodes total)
// ---------------------------------------------------------------------------
__global__ void prep(const float4* __restrict__ x) {
    size_t i = (size_t)blockIdx.x * blockDim.x + threadIdx.x;
    if (i < 2 * T_LEN * 8) g_cnt[i] = 0;
    float4 v = x[i];
    v.x = tfr(v.x); v.y = tfr(v.y); v.z = tfr(v.z); v.w = tfr(v.w);
    ((float4*)g_xr)[i] = v;
}

// ---------------------------------------------------------------------------
// Launch: 2 graph nodes
// ---------------------------------------------------------------------------
extern "C" void kernel_launch(void* const* d_in, const int* in_sizes, int n_in,
                              void* d_out, int out_size) {
    const float* x   = (const float*)d_in[0];
    const float* Wx0 = (const float*)d_in[1];
    const float* bx0 = (const float*)d_in[2];
    const float* Wh0 = (const float*)d_in[3];
    const float* bh0 = (const float*)d_in[4];
    const float* Wx1 = (const float*)d_in[5];
    const float* bx1 = (const float*)d_in[6];
    const float* Wh1 = (const float*)d_in[7];
    const float* bh1 = (const float*)d_in[8];

    const size_t SMEM_BYTES =
        (size_t)(32 * WPITCH0 + 8 * NBUF * BUFSZ + 512 + 32) * sizeof(float);
    cudaFuncSetAttribute(lstm_fused, cudaFuncAttributeMaxDynamicSharedMemorySize,
                         (int)SMEM_BYTES);

    prep<<<4096, 1024>>>((const float4*)x);
    lstm_fused<<<128, 256, SMEM_BYTES>>>(Wx0, bx0, Wh0, bh0,
                                         Wx1, bx1, Wh1, bh1, (float*)d_out);
}